// round 5
// baseline (speedup 1.0000x reference)
#include <cuda_runtime.h>
#include <math.h>
#include <stdint.h>

#define Bb 4
#define S 2048
#define D 512
#define H 4
#define HD 128
#define M_TOT (Bb*S)      // 8192
#define D2 (2*D)          // 1024
#define LN_EPS 1e-5f

// ------------------------------------------------------------------ scratch
__device__ float g_h[(size_t)M_TOT * D2];
__device__ float g_se_pre[(size_t)M_TOT * D];
__device__ float g_se[(size_t)M_TOT * D];
__device__ float g_qk[2 * (size_t)M_TOT * D];     // q then k
__device__ float g_vt[(size_t)M_TOT * D];         // [B][D][S] (V^T per batch)
__device__ float g_ctx[(size_t)M_TOT * D];
__device__ float g_wet[1024 * 512];               // We^T [1024,512]
__device__ float g_wst[512 * 1024];               // Ws^T [512,1024]
__device__ float g_wqkv[3 * 512 * 512];           // Wq^T,Wk^T,Wv^T

// ------------------------------------------------------------------ utils
__device__ __forceinline__ uint32_t f2tf(float f) {
    uint32_t u; asm("cvt.rna.tf32.f32 %0, %1;" : "=r"(u) : "f"(f)); return u;
}

__device__ __forceinline__ void mma_tf32(float c[4], const uint32_t a[4], const uint32_t b[2]) {
    asm volatile(
        "mma.sync.aligned.m16n8k8.row.col.f32.tf32.tf32.f32 "
        "{%0,%1,%2,%3}, {%4,%5,%6,%7}, {%8,%9}, {%0,%1,%2,%3};"
        : "+f"(c[0]), "+f"(c[1]), "+f"(c[2]), "+f"(c[3])
        : "r"(a[0]), "r"(a[1]), "r"(a[2]), "r"(a[3]), "r"(b[0]), "r"(b[1]));
}

// Permuted column layout: within each 8-col k-group, logical col c sits at
// physical 2*(c&3) + ((c>>2)&1). So (k+tig, k+tig+4) -> adjacent pair at
// physical k + 2*tig, loadable with one ld.shared.v2.
#define LDA 40    // padded smem leading dim (gemm)  — 8*gid+2*tig conflict-free per half-warp
#define FLDA 136  // padded smem leading dim (flash) — 136 mod 32 == 8, same property

// ================================================================== GEMM path
__device__ __forceinline__ void mma_mainloop(
    const float* __restrict__ Ap, long long lda,
    const float* __restrict__ Bp, long long ldb,
    int K, uint32_t (*As)[LDA], uint32_t (*Bs)[LDA], float acc[4][4][4])
{
    const int tid  = threadIdx.x;
    const int w    = tid >> 5, lane = tid & 31;
    const int gid  = lane >> 2, tig = lane & 3;
    const int wm   = w & 1, wn = w >> 1;

    const int srow = tid >> 3;          // 0..31 (stage row base, +32 per rep)
    const int sc4  = (tid & 7) * 4;     // logical col base 0..28
    const int sbase = (sc4 & ~7) + ((sc4 >> 2) & 1);   // permuted store base, stride 2

    float4 pa[4], pb[4];
#pragma unroll
    for (int i = 0; i < 4; i++) {
        pa[i] = *(const float4*)(Ap + (long long)(srow + i * 32) * lda + sc4);
        pb[i] = *(const float4*)(Bp + (long long)(srow + i * 32) * ldb + sc4);
    }

    const int nchunk = K >> 5;
    for (int c = 0; c < nchunk; c++) {
        __syncthreads();
#pragma unroll
        for (int i = 0; i < 4; i++) {
            const int r = srow + i * 32;
            uint32_t* da = &As[r][sbase];
            da[0] = f2tf(pa[i].x); da[2] = f2tf(pa[i].y);
            da[4] = f2tf(pa[i].z); da[6] = f2tf(pa[i].w);
            uint32_t* db = &Bs[r][sbase];
            db[0] = f2tf(pb[i].x); db[2] = f2tf(pb[i].y);
            db[4] = f2tf(pb[i].z); db[6] = f2tf(pb[i].w);
        }
        __syncthreads();

        if (c + 1 < nchunk) {
            const int k0 = (c + 1) << 5;
#pragma unroll
            for (int i = 0; i < 4; i++) {
                pa[i] = *(const float4*)(Ap + (long long)(srow + i * 32) * lda + k0 + sc4);
                pb[i] = *(const float4*)(Bp + (long long)(srow + i * 32) * ldb + k0 + sc4);
            }
        }

#pragma unroll
        for (int k8 = 0; k8 < 4; k8++) {
            const int co = k8 * 8 + tig * 2;
            uint32_t af[4][4], bf[4][2];
#pragma unroll
            for (int mt = 0; mt < 4; mt++) {
                const int r = wm * 64 + mt * 16 + gid;
                const uint2 a0 = *(const uint2*)&As[r][co];
                const uint2 a1 = *(const uint2*)&As[r + 8][co];
                af[mt][0] = a0.x; af[mt][1] = a1.x; af[mt][2] = a0.y; af[mt][3] = a1.y;
            }
#pragma unroll
            for (int nt = 0; nt < 4; nt++) {
                const int n = wn * 32 + nt * 8 + gid;
                const uint2 b0 = *(const uint2*)&Bs[n][co];
                bf[nt][0] = b0.x; bf[nt][1] = b0.y;
            }
#pragma unroll
            for (int mt = 0; mt < 4; mt++)
#pragma unroll
                for (int nt = 0; nt < 4; nt++)
                    mma_tf32(acc[mt][nt], af[mt], bf[nt]);
        }
    }
}

__global__ void __launch_bounds__(256)
mma_gemm(const float* __restrict__ A, long long lda, long long Azb, long long Azh,
         const float* __restrict__ Bt, long long ldb, long long Bzb, long long Bzh,
         float* __restrict__ C, long long ldc, long long Czb, long long Czh,
         const float* b0, const float* b1, const float* b2,
         const float* __restrict__ resid, float* __restrict__ vt, int vt_z,
         int relu, int K, int zdiv)
{
    __shared__ __align__(16) uint32_t As[128][LDA];
    __shared__ __align__(16) uint32_t Bs[128][LDA];

    const int tid = threadIdx.x;
    const int z = blockIdx.z;
    const long long zb = z / zdiv, zh = z % zdiv;

    const float* Ap = A + zb * Azb + zh * Azh + (long long)blockIdx.y * 128 * lda;
    const float* Bp = Bt + zb * Bzb + zh * Bzh + (long long)blockIdx.x * 128 * ldb;

    float acc[4][4][4];
#pragma unroll
    for (int i = 0; i < 4; i++)
#pragma unroll
        for (int j = 0; j < 4; j++)
#pragma unroll
            for (int e = 0; e < 4; e++) acc[i][j][e] = 0.f;

    mma_mainloop(Ap, lda, Bp, ldb, K, As, Bs, acc);

    const float* bias = (z == 0) ? b0 : (z == 1) ? b1 : b2;
    const int w = tid >> 5, lane = tid & 31;
    const int gid = lane >> 2, tig = lane & 3;
    const int wm = w & 1, wn = w >> 1;
    float* Cz = C + zb * Czb + zh * Czh;
    const bool dotrans = (vt != nullptr) && (z == vt_z);

#pragma unroll
    for (int mt = 0; mt < 4; mt++) {
        const long long r0 = (long long)blockIdx.y * 128 + wm * 64 + mt * 16 + gid;
        const long long r1 = r0 + 8;
#pragma unroll
        for (int nt = 0; nt < 4; nt++) {
            const long long cb = (long long)blockIdx.x * 128 + wn * 32 + nt * 8 + tig * 2;
            float v0 = acc[mt][nt][0], v1 = acc[mt][nt][1];
            float v2 = acc[mt][nt][2], v3 = acc[mt][nt][3];
            if (bias) {
                const float bx = __ldg(bias + cb), by = __ldg(bias + cb + 1);
                v0 += bx; v1 += by; v2 += bx; v3 += by;
            }
            if (resid) {
                const float2 q0 = *(const float2*)(resid + r0 * ldc + cb);
                const float2 q1 = *(const float2*)(resid + r1 * ldc + cb);
                v0 += q0.x; v1 += q0.y; v2 += q1.x; v3 += q1.y;
            }
            if (relu) {
                v0 = fmaxf(v0, 0.f); v1 = fmaxf(v1, 0.f);
                v2 = fmaxf(v2, 0.f); v3 = fmaxf(v3, 0.f);
            }
            if (dotrans) {
                const long long b0r = r0 >> 11, s0 = r0 & (S - 1);
                const long long b1r = r1 >> 11, s1 = r1 & (S - 1);
                float* vb0 = vt + b0r * ((long long)D * S);
                float* vb1 = vt + b1r * ((long long)D * S);
                vb0[cb * S + s0] = v0; vb0[(cb + 1) * S + s0] = v1;
                vb1[cb * S + s1] = v2; vb1[(cb + 1) * S + s1] = v3;
            } else {
                *(float2*)(Cz + r0 * ldc + cb) = make_float2(v0, v1);
                *(float2*)(Cz + r1 * ldc + cb) = make_float2(v2, v3);
            }
        }
    }
}

// ================================================================== flash attention
__global__ void __launch_bounds__(256)
flash_kernel(const float* __restrict__ qbase, const float* __restrict__ kbase,
             const float* __restrict__ pos, const float* __restrict__ alpha_p)
{
    extern __shared__ uint32_t sm[];
    uint32_t (*Qs)[FLDA] = (uint32_t(*)[FLDA])sm;
    uint32_t (*Ks)[FLDA] = (uint32_t(*)[FLDA])(sm + 128 * FLDA);
    uint32_t (*Vs)[FLDA] = (uint32_t(*)[FLDA])(sm + 2 * 128 * FLDA);
    float4* spos = (float4*)(sm + 3 * 128 * FLDA);

    const int tid  = threadIdx.x;
    const int w    = tid >> 5, lane = tid & 31;
    const int gid  = lane >> 2, tig = lane & 3;
    const int z    = blockIdx.y;
    const long long b = z / H, h = z % H;
    const int qt   = blockIdx.x;

    const float* Qp = qbase + b * ((long long)S * D) + h * HD + (long long)qt * 128 * D;
    const float* Kb = kbase + b * ((long long)S * D) + h * HD;
    const float* Vb = g_vt + b * ((long long)D * S) + (long long)h * HD * S;  // [hd][s]
    const float* pb = pos + b * ((long long)S * 3);

    // permuted store base for staging: lane covers logical cols lane*4..lane*4+3
    const int sc4   = lane * 4;
    const int sbase = (sc4 & ~7) + ((sc4 >> 2) & 1);

    // stage Q tile (tf32, permuted cols)
#pragma unroll
    for (int i = 0; i < 16; i++) {
        const int r = w + 8 * i;
        const float4 v = *(const float4*)(Qp + (long long)r * D + sc4);
        uint32_t* dst = &Qs[r][sbase];
        dst[0] = f2tf(v.x); dst[2] = f2tf(v.y); dst[4] = f2tf(v.z); dst[6] = f2tf(v.w);
    }

    const long long gr0 = (long long)qt * 128 + w * 16 + gid;
    const long long gr1 = gr0 + 8;
    const float px0 = __ldg(pb + gr0 * 3), py0 = __ldg(pb + gr0 * 3 + 1), pz0 = __ldg(pb + gr0 * 3 + 2);
    const float px1 = __ldg(pb + gr1 * 3), py1 = __ldg(pb + gr1 * 3 + 1), pz1 = __ldg(pb + gr1 * 3 + 2);
    const float sq0 = px0 * px0 + py0 * py0 + pz0 * pz0;
    const float sq1 = px1 * px1 + py1 * py1 + pz1 * pz1;

    float oacc[16][4];
#pragma unroll
    for (int i = 0; i < 16; i++)
#pragma unroll
        for (int e = 0; e < 4; e++) oacc[i][e] = 0.f;
    float m0 = -1e30f, m1 = -1e30f, l0 = 0.f, l1 = 0.f;

    const float scale = 0.08838834764831845f;  // 1/sqrt(128)
    const float alpha = __ldg(alpha_p);
    const int src0 = (lane & ~3) | (tig >> 1);
    const int src1 = src0 + 2;
    const bool odd = (tig & 1);

    for (int j = 0; j < 16; j++) {
        __syncthreads();
        const float* Kp = Kb + (long long)j * 128 * D;
#pragma unroll
        for (int i = 0; i < 16; i++) {
            const int r = w + 8 * i;
            const float4 v = *(const float4*)(Kp + (long long)r * D + sc4);
            uint32_t* dk = &Ks[r][sbase];
            dk[0] = f2tf(v.x); dk[2] = f2tf(v.y); dk[4] = f2tf(v.z); dk[6] = f2tf(v.w);
            const float4 u = *(const float4*)(Vb + (long long)r * S + j * 128 + sc4);
            uint32_t* dv = &Vs[r][sbase];
            dv[0] = f2tf(u.x); dv[2] = f2tf(u.y); dv[4] = f2tf(u.z); dv[6] = f2tf(u.w);
        }
        if (tid < 128) {
            const long long c = (long long)j * 128 + tid;
            const float x = pb[c * 3], y = pb[c * 3 + 1], zz = pb[c * 3 + 2];
            spos[tid] = make_float4(x, y, zz, x * x + y * y + zz * zz);
        }
        __syncthreads();

        // ---- S = Q @ K^T ----
        float sacc[16][4];
#pragma unroll
        for (int i = 0; i < 16; i++)
#pragma unroll
            for (int e = 0; e < 4; e++) sacc[i][e] = 0.f;

        const int ra = w * 16 + gid;
#pragma unroll
        for (int g = 0; g < 16; g++) {
            const int co = g * 8 + tig * 2;
            const uint2 a0 = *(const uint2*)&Qs[ra][co];
            const uint2 a1 = *(const uint2*)&Qs[ra + 8][co];
            uint32_t af[4] = { a0.x, a1.x, a0.y, a1.y };
#pragma unroll
            for (int nt = 0; nt < 16; nt++) {
                const uint2 bb = *(const uint2*)&Ks[nt * 8 + gid][co];
                uint32_t bf[2] = { bb.x, bb.y };
                mma_tf32(sacc[nt], af, bf);
            }
        }

        // ---- bias + online softmax ----
        float nm0 = m0, nm1 = m1;
#pragma unroll
        for (int nt = 0; nt < 16; nt++) {
            const int c0 = nt * 8 + tig * 2;
            const float4 q0 = spos[c0];
            const float4 q1 = spos[c0 + 1];
            float d;
            d = fmaxf(sq0 + q0.w - 2.f * (px0 * q0.x + py0 * q0.y + pz0 * q0.z), 0.f);
            sacc[nt][0] = sacc[nt][0] * scale - alpha * d;
            d = fmaxf(sq0 + q1.w - 2.f * (px0 * q1.x + py0 * q1.y + pz0 * q1.z), 0.f);
            sacc[nt][1] = sacc[nt][1] * scale - alpha * d;
            d = fmaxf(sq1 + q0.w - 2.f * (px1 * q0.x + py1 * q0.y + pz1 * q0.z), 0.f);
            sacc[nt][2] = sacc[nt][2] * scale - alpha * d;
            d = fmaxf(sq1 + q1.w - 2.f * (px1 * q1.x + py1 * q1.y + pz1 * q1.z), 0.f);
            sacc[nt][3] = sacc[nt][3] * scale - alpha * d;
            nm0 = fmaxf(nm0, fmaxf(sacc[nt][0], sacc[nt][1]));
            nm1 = fmaxf(nm1, fmaxf(sacc[nt][2], sacc[nt][3]));
        }
        nm0 = fmaxf(nm0, __shfl_xor_sync(0xffffffffu, nm0, 1));
        nm0 = fmaxf(nm0, __shfl_xor_sync(0xffffffffu, nm0, 2));
        nm1 = fmaxf(nm1, __shfl_xor_sync(0xffffffffu, nm1, 1));
        nm1 = fmaxf(nm1, __shfl_xor_sync(0xffffffffu, nm1, 2));

        const float f0 = __expf(m0 - nm0);
        const float f1 = __expf(m1 - nm1);
        m0 = nm0; m1 = nm1;

        float rs0 = 0.f, rs1 = 0.f;
#pragma unroll
        for (int nt = 0; nt < 16; nt++) {
            sacc[nt][0] = __expf(sacc[nt][0] - nm0);
            sacc[nt][1] = __expf(sacc[nt][1] - nm0);
            sacc[nt][2] = __expf(sacc[nt][2] - nm1);
            sacc[nt][3] = __expf(sacc[nt][3] - nm1);
            rs0 += sacc[nt][0] + sacc[nt][1];
            rs1 += sacc[nt][2] + sacc[nt][3];
        }
        rs0 += __shfl_xor_sync(0xffffffffu, rs0, 1);
        rs0 += __shfl_xor_sync(0xffffffffu, rs0, 2);
        rs1 += __shfl_xor_sync(0xffffffffu, rs1, 1);
        rs1 += __shfl_xor_sync(0xffffffffu, rs1, 2);
        l0 = l0 * f0 + rs0;
        l1 = l1 * f1 + rs1;

#pragma unroll
        for (int i = 0; i < 16; i++) {
            oacc[i][0] *= f0; oacc[i][1] *= f0;
            oacc[i][2] *= f1; oacc[i][3] *= f1;
        }

        // ---- O += P @ V ----
#pragma unroll
        for (int g = 0; g < 16; g++) {
            const float u00 = __shfl_sync(0xffffffffu, sacc[g][0], src0);
            const float u01 = __shfl_sync(0xffffffffu, sacc[g][1], src0);
            const float u10 = __shfl_sync(0xffffffffu, sacc[g][0], src1);
            const float u11 = __shfl_sync(0xffffffffu, sacc[g][1], src1);
            const float u20 = __shfl_sync(0xffffffffu, sacc[g][2], src0);
            const float u21 = __shfl_sync(0xffffffffu, sacc[g][3], src0);
            const float u30 = __shfl_sync(0xffffffffu, sacc[g][2], src1);
            const float u31 = __shfl_sync(0xffffffffu, sacc[g][3], src1);
            uint32_t af[4];
            af[0] = f2tf(odd ? u01 : u00);   // P[row0][tig]
            af[1] = f2tf(odd ? u21 : u20);   // P[row1][tig]
            af[2] = f2tf(odd ? u11 : u10);   // P[row0][tig+4]
            af[3] = f2tf(odd ? u31 : u30);   // P[row1][tig+4]
            const int co = g * 8 + tig * 2;
#pragma unroll
            for (int ng = 0; ng < 16; ng++) {
                const uint2 bb = *(const uint2*)&Vs[ng * 8 + gid][co];
                uint32_t bf[2] = { bb.x, bb.y };
                mma_tf32(oacc[ng], af, bf);
            }
        }
    }

    // ---- epilogue: O / l -> ctx ----
    const float i0 = 1.f / l0, i1 = 1.f / l1;
    float* Cb = g_ctx + b * ((long long)S * D) + h * HD;
    const long long cr0 = (long long)qt * 128 + w * 16 + gid;
#pragma unroll
    for (int ng = 0; ng < 16; ng++) {
        const int col = ng * 8 + tig * 2;
        *(float2*)(Cb + cr0 * D + col)       = make_float2(oacc[ng][0] * i0, oacc[ng][1] * i0);
        *(float2*)(Cb + (cr0 + 8) * D + col) = make_float2(oacc[ng][2] * i1, oacc[ng][3] * i1);
    }
}

// ------------------------------------------------------------------ transpose [R,C] -> [C,R]
__global__ void transpose_kernel(const float* __restrict__ in, float* __restrict__ out,
                                 int R, int C)
{
    __shared__ float t[32][33];
    const int bx = blockIdx.x * 32, by = blockIdx.y * 32;
    const int tx = threadIdx.x, ty = threadIdx.y;
#pragma unroll
    for (int dy = 0; dy < 32; dy += 8)
        t[ty + dy][tx] = in[(size_t)(by + ty + dy) * C + bx + tx];
    __syncthreads();
#pragma unroll
    for (int dy = 0; dy < 32; dy += 8)
        out[(size_t)(bx + ty + dy) * R + by + tx] = t[tx][ty + dy];
}

// ------------------------------------------------------------------ LayerNorm
__global__ void ln_kernel(const float* __restrict__ x, const float* __restrict__ x2,
                          const float* __restrict__ gamma, const float* __restrict__ beta,
                          float* __restrict__ out)
{
    __shared__ float red[128];
    const int row = blockIdx.x, t = threadIdx.x;
    const size_t base = (size_t)row * D + t * 4;

    float4 v = *(const float4*)(x + base);
    if (x2) {
        float4 w = *(const float4*)(x2 + base);
        v.x += w.x; v.y += w.y; v.z += w.z; v.w += w.w;
    }
    red[t] = v.x + v.y + v.z + v.w; __syncthreads();
    for (int s2 = 64; s2 > 0; s2 >>= 1) {
        if (t < s2) red[t] += red[t + s2];
        __syncthreads();
    }
    const float mean = red[0] * (1.f / D); __syncthreads();

    float dx = v.x - mean, dy = v.y - mean, dz = v.z - mean, dw = v.w - mean;
    red[t] = dx * dx + dy * dy + dz * dz + dw * dw; __syncthreads();
    for (int s2 = 64; s2 > 0; s2 >>= 1) {
        if (t < s2) red[t] += red[t + s2];
        __syncthreads();
    }
    const float inv = rsqrtf(red[0] * (1.f / D) + LN_EPS);

    float4 g = *(const float4*)(gamma + t * 4);
    float4 bt = *(const float4*)(beta + t * 4);
    float4 o;
    o.x = dx * inv * g.x + bt.x;
    o.y = dy * inv * g.y + bt.y;
    o.z = dz * inv * g.z + bt.z;
    o.w = dw * inv * g.w + bt.w;
    *(float4*)(out + base) = o;
}

// ------------------------------------------------------------------ host
extern "C" void kernel_launch(void* const* d_in, const int* in_sizes, int n_in,
                              void* d_out, int out_size)
{
    const float* input   = (const float*)d_in[0];
    const float* pos     = (const float*)d_in[1];
    const float* We      = (const float*)d_in[2];
    const float* be      = (const float*)d_in[3];
    const float* Ws      = (const float*)d_in[4];
    const float* bs      = (const float*)d_in[5];
    const float* gamma   = (const float*)d_in[6];
    const float* beta    = (const float*)d_in[7];
    const float* Wq      = (const float*)d_in[8];
    const float* bq      = (const float*)d_in[9];
    const float* Wk      = (const float*)d_in[10];
    const float* bk      = (const float*)d_in[11];
    const float* Wv      = (const float*)d_in[12];
    const float* bv      = (const float*)d_in[13];
    const float* alpha_p = (const float*)d_in[14];
    float* out = (float*)d_out;

    float *h, *se_pre, *se, *qk, *vt, *ctx, *wet, *wst, *wqkv;
    cudaGetSymbolAddress((void**)&h,      g_h);
    cudaGetSymbolAddress((void**)&se_pre, g_se_pre);
    cudaGetSymbolAddress((void**)&se,     g_se);
    cudaGetSymbolAddress((void**)&qk,     g_qk);
    cudaGetSymbolAddress((void**)&vt,     g_vt);
    cudaGetSymbolAddress((void**)&ctx,    g_ctx);
    cudaGetSymbolAddress((void**)&wet,    g_wet);
    cudaGetSymbolAddress((void**)&wst,    g_wst);
    cudaGetSymbolAddress((void**)&wqkv,   g_wqkv);

    static bool attr_set = false;
    const int flash_smem = (3 * 128 * FLDA) * 4 + 128 * 16;   // 210944 B
    if (!attr_set) {
        cudaFuncSetAttribute(flash_kernel, cudaFuncAttributeMaxDynamicSharedMemorySize, flash_smem);
        attr_set = true;
    }

    dim3 tb(32, 8);
    transpose_kernel<<<dim3(D2 / 32, D / 32),  tb>>>(We, wet, D, D2);
    transpose_kernel<<<dim3(D / 32,  D2 / 32), tb>>>(Ws, wst, D2, D);
    transpose_kernel<<<dim3(D / 32,  D / 32),  tb>>>(Wq, wqkv + 0 * D * D, D, D);
    transpose_kernel<<<dim3(D / 32,  D / 32),  tb>>>(Wk, wqkv + 1 * D * D, D, D);
    transpose_kernel<<<dim3(D / 32,  D / 32),  tb>>>(Wv, wqkv + 2 * D * D, D, D);

    // 1. h = relu(input @ We + be)
    mma_gemm<<<dim3(D2 / 128, M_TOT / 128, 1), 256>>>(
        input, D, 0, 0,  wet, D, 0, 0,  h, D2, 0, 0,
        be, be, be, nullptr, nullptr, -1, 1, D, 1);
    // 2. se_pre = input + h @ Ws + bs
    mma_gemm<<<dim3(D / 128, M_TOT / 128, 1), 256>>>(
        h, D2, 0, 0,  wst, D2, 0, 0,  se_pre, D, 0, 0,
        bs, bs, bs, input, nullptr, -1, 0, D2, 1);
    // 3. se = LN(se_pre)
    ln_kernel<<<M_TOT, 128>>>(se_pre, nullptr, gamma, beta, se);
    // 4. q/k/v (z=0,1,2); v written transposed into g_vt
    mma_gemm<<<dim3(D / 128, M_TOT / 128, 3), 256>>>(
        se, D, 0, 0,
        wqkv, D, (long long)D * D, 0,
        qk, D, (long long)M_TOT * D, 0,
        bq, bk, bv, nullptr, vt, 2, 0, D, 1);
    // 5-7. fused flash attention -> ctx
    flash_kernel<<<dim3(S / 128, Bb * H), 256, flash_smem>>>(
        qk, qk + (size_t)M_TOT * D, pos, alpha_p);
    // 8. out = LN(se + ctx)
    ln_kernel<<<M_TOT, 128>>>(se, ctx, gamma, beta, out);
}

// round 6
// speedup vs baseline: 1.0430x; 1.0430x over previous
#include <cuda_runtime.h>
#include <math.h>
#include <stdint.h>

#define Bb 4
#define S 2048
#define D 512
#define H 4
#define HD 128
#define M_TOT (Bb*S)      // 8192
#define D2 (2*D)          // 1024
#define LN_EPS 1e-5f

// ------------------------------------------------------------------ scratch
__device__ float g_h[(size_t)M_TOT * D2];
__device__ float g_se_pre[(size_t)M_TOT * D];
__device__ float g_se[(size_t)M_TOT * D];
__device__ float g_qk[2 * (size_t)M_TOT * D];     // q then k
__device__ float g_vt[(size_t)M_TOT * D];         // [B][D][S] (V^T per batch)
__device__ float g_ctx[(size_t)M_TOT * D];
__device__ float g_wet[1024 * 512];               // We^T [1024,512]
__device__ float g_wst[512 * 1024];               // Ws^T [512,1024]
__device__ float g_wqkv[3 * 512 * 512];           // Wq^T,Wk^T,Wv^T

// ------------------------------------------------------------------ utils
__device__ __forceinline__ uint32_t f2tf(float f) {
    uint32_t u; asm("cvt.rna.tf32.f32 %0, %1;" : "=r"(u) : "f"(f)); return u;
}

__device__ __forceinline__ void mma_tf32(float c[4], const uint32_t a[4], const uint32_t b[2]) {
    asm volatile(
        "mma.sync.aligned.m16n8k8.row.col.f32.tf32.tf32.f32 "
        "{%0,%1,%2,%3}, {%4,%5,%6,%7}, {%8,%9}, {%0,%1,%2,%3};"
        : "+f"(c[0]), "+f"(c[1]), "+f"(c[2]), "+f"(c[3])
        : "r"(a[0]), "r"(a[1]), "r"(a[2]), "r"(a[3]), "r"(b[0]), "r"(b[1]));
}

// Permuted column layout: logical col c at physical (c&~7) + 2*(c&3) + ((c>>2)&1).
// Fragment pair (k+tig, k+tig+4) -> adjacent physical (k+2tig, k+2tig+1): one LDS.64.
// Staging thread owning logical cols {c0,c0+1,c0+4,c0+5} (c0 = 8g+2t) stores them
// contiguously at physical 8g+4t as {lo.x, hi.x, lo.y, hi.y}: one STS.128.
#define LDA 40    // ≡8 mod 32: v2 frag loads conflict-free per half-warp
#define FLDA 136  // ≡8 mod 32: same property

// ================================================================== GEMM path
// Double-buffered, one sync per 32-wide K chunk, register prefetch 1 chunk ahead.
__device__ __forceinline__ void mma_mainloop(
    const float* __restrict__ Ap, long long lda,
    const float* __restrict__ Bp, long long ldb,
    int K, uint32_t* dsm, float acc[4][4][4])
{
    const int tid  = threadIdx.x;
    const int lane = tid & 31;
    const int gid  = lane >> 2, tig = lane & 3;
    const int w    = tid >> 5;
    const int wm   = w & 1, wn = w >> 1;

    const int srow = tid >> 3;                    // 0..31 (+32 per rep)
    const int u    = tid & 7;
    const int c0   = (u >> 1) * 8 + (u & 1) * 2;  // logical col pair base
    const int sp   = (u >> 1) * 8 + (u & 1) * 4;  // physical store col (v4)

    uint32_t* Abuf[2] = { dsm,               dsm + 128 * LDA };
    uint32_t* Bbuf[2] = { dsm + 2*128*LDA,   dsm + 3*128*LDA };

    float2 la[4][2], lb[4][2];

#define LDCHUNK(k0) do { \
    _Pragma("unroll") \
    for (int i = 0; i < 4; i++) { \
        const float* ar = Ap + (long long)(srow + 32 * i) * lda + (k0); \
        la[i][0] = *(const float2*)(ar + c0); \
        la[i][1] = *(const float2*)(ar + c0 + 4); \
        const float* br = Bp + (long long)(srow + 32 * i) * ldb + (k0); \
        lb[i][0] = *(const float2*)(br + c0); \
        lb[i][1] = *(const float2*)(br + c0 + 4); \
    } } while (0)

#define STCHUNK(s) do { \
    _Pragma("unroll") \
    for (int i = 0; i < 4; i++) { \
        const int r = srow + 32 * i; \
        uint4 va = make_uint4(f2tf(la[i][0].x), f2tf(la[i][1].x), f2tf(la[i][0].y), f2tf(la[i][1].y)); \
        *(uint4*)&Abuf[s][r * LDA + sp] = va; \
        uint4 vb = make_uint4(f2tf(lb[i][0].x), f2tf(lb[i][1].x), f2tf(lb[i][0].y), f2tf(lb[i][1].y)); \
        *(uint4*)&Bbuf[s][r * LDA + sp] = vb; \
    } } while (0)

    const int nchunk = K >> 5;
    LDCHUNK(0);
    STCHUNK(0);
    if (nchunk > 1) LDCHUNK(32);
    __syncthreads();

    for (int c = 0; c < nchunk; c++) {
        if (c + 1 < nchunk) STCHUNK((c + 1) & 1);      // regs hold chunk c+1
        if (c + 2 < nchunk) LDCHUNK((c + 2) << 5);     // prefetch chunk c+2
        const uint32_t* Ab = Abuf[c & 1];
        const uint32_t* Bs = Bbuf[c & 1];

#pragma unroll
        for (int k8 = 0; k8 < 4; k8++) {
            const int co = k8 * 8 + tig * 2;
            uint32_t af[4][4], bf[4][2];
#pragma unroll
            for (int mt = 0; mt < 4; mt++) {
                const int r = wm * 64 + mt * 16 + gid;
                const uint2 a0 = *(const uint2*)&Ab[r * LDA + co];
                const uint2 a1 = *(const uint2*)&Ab[(r + 8) * LDA + co];
                af[mt][0] = a0.x; af[mt][1] = a1.x; af[mt][2] = a0.y; af[mt][3] = a1.y;
            }
#pragma unroll
            for (int nt = 0; nt < 4; nt++) {
                const int n = wn * 32 + nt * 8 + gid;
                const uint2 b0 = *(const uint2*)&Bs[n * LDA + co];
                bf[nt][0] = b0.x; bf[nt][1] = b0.y;
            }
#pragma unroll
            for (int mt = 0; mt < 4; mt++)
#pragma unroll
                for (int nt = 0; nt < 4; nt++)
                    mma_tf32(acc[mt][nt], af[mt], bf[nt]);
        }
        __syncthreads();
    }
#undef LDCHUNK
#undef STCHUNK
}

__global__ void __launch_bounds__(256)
mma_gemm(const float* __restrict__ A, long long lda, long long Azb, long long Azh,
         const float* __restrict__ Bt, long long ldb, long long Bzb, long long Bzh,
         float* __restrict__ C, long long ldc, long long Czb, long long Czh,
         const float* b0, const float* b1, const float* b2,
         const float* __restrict__ resid, float* __restrict__ vt, int vt_z,
         int relu, int K, int zdiv)
{
    extern __shared__ uint32_t dsm[];

    const int tid = threadIdx.x;
    const int z = blockIdx.z;
    const long long zb = z / zdiv, zh = z % zdiv;

    const float* Ap = A + zb * Azb + zh * Azh + (long long)blockIdx.y * 128 * lda;
    const float* Bp = Bt + zb * Bzb + zh * Bzh + (long long)blockIdx.x * 128 * ldb;

    float acc[4][4][4];
#pragma unroll
    for (int i = 0; i < 4; i++)
#pragma unroll
        for (int j = 0; j < 4; j++)
#pragma unroll
            for (int e = 0; e < 4; e++) acc[i][j][e] = 0.f;

    mma_mainloop(Ap, lda, Bp, ldb, K, dsm, acc);

    const float* bias = (z == 0) ? b0 : (z == 1) ? b1 : b2;
    const int w = tid >> 5, lane = tid & 31;
    const int gid = lane >> 2, tig = lane & 3;
    const int wm = w & 1, wn = w >> 1;
    float* Cz = C + zb * Czb + zh * Czh;
    const bool dotrans = (vt != nullptr) && (z == vt_z);

#pragma unroll
    for (int mt = 0; mt < 4; mt++) {
        const long long r0 = (long long)blockIdx.y * 128 + wm * 64 + mt * 16 + gid;
        const long long r1 = r0 + 8;
#pragma unroll
        for (int nt = 0; nt < 4; nt++) {
            const long long cb = (long long)blockIdx.x * 128 + wn * 32 + nt * 8 + tig * 2;
            float v0 = acc[mt][nt][0], v1 = acc[mt][nt][1];
            float v2 = acc[mt][nt][2], v3 = acc[mt][nt][3];
            if (bias) {
                const float bx = __ldg(bias + cb), by = __ldg(bias + cb + 1);
                v0 += bx; v1 += by; v2 += bx; v3 += by;
            }
            if (resid) {
                const float2 q0 = *(const float2*)(resid + r0 * ldc + cb);
                const float2 q1 = *(const float2*)(resid + r1 * ldc + cb);
                v0 += q0.x; v1 += q0.y; v2 += q1.x; v3 += q1.y;
            }
            if (relu) {
                v0 = fmaxf(v0, 0.f); v1 = fmaxf(v1, 0.f);
                v2 = fmaxf(v2, 0.f); v3 = fmaxf(v3, 0.f);
            }
            if (dotrans) {
                const long long b0r = r0 >> 11, s0 = r0 & (S - 1);
                const long long b1r = r1 >> 11, s1 = r1 & (S - 1);
                float* vb0 = vt + b0r * ((long long)D * S);
                float* vb1 = vt + b1r * ((long long)D * S);
                vb0[cb * S + s0] = v0; vb0[(cb + 1) * S + s0] = v1;
                vb1[cb * S + s1] = v2; vb1[(cb + 1) * S + s1] = v3;
            } else {
                *(float2*)(Cz + r0 * ldc + cb) = make_float2(v0, v1);
                *(float2*)(Cz + r1 * ldc + cb) = make_float2(v2, v3);
            }
        }
    }
}

// ================================================================== flash attention
__global__ void __launch_bounds__(256)
flash_kernel(const float* __restrict__ qbase, const float* __restrict__ kbase,
             const float* __restrict__ pos, const float* __restrict__ alpha_p)
{
    extern __shared__ uint32_t sm[];
    uint32_t (*Qs)[FLDA] = (uint32_t(*)[FLDA])sm;
    uint32_t (*Ks)[FLDA] = (uint32_t(*)[FLDA])(sm + 128 * FLDA);
    uint32_t (*Vs)[FLDA] = (uint32_t(*)[FLDA])(sm + 2 * 128 * FLDA);
    float4* spos = (float4*)(sm + 3 * 128 * FLDA);

    const int tid  = threadIdx.x;
    const int w    = tid >> 5, lane = tid & 31;
    const int gid  = lane >> 2, tig = lane & 3;
    const int z    = blockIdx.y;
    const long long b = z / H, h = z % H;
    const int qt   = blockIdx.x;

    const float* Qp = qbase + b * ((long long)S * D) + h * HD + (long long)qt * 128 * D;
    const float* Kb = kbase + b * ((long long)S * D) + h * HD;
    const float* Vb = g_vt + b * ((long long)D * S) + (long long)h * HD * S;  // [hd][s]
    const float* pb = pos + b * ((long long)S * 3);

    // staging: lane covers logical cols {c0,c0+1,c0+4,c0+5}, c0 = 8*(lane>>1)+2*(lane&1);
    // stores contiguously at physical 4*lane (one STS.128).
    const int fc0 = (lane >> 1) * 8 + (lane & 1) * 2;
    const int fsp = lane * 4;

    // stage Q tile (tf32, permuted cols)
#pragma unroll
    for (int i = 0; i < 16; i++) {
        const int r = w + 8 * i;
        const float2 qlo = *(const float2*)(Qp + (long long)r * D + fc0);
        const float2 qhi = *(const float2*)(Qp + (long long)r * D + fc0 + 4);
        *(uint4*)&Qs[r][fsp] = make_uint4(f2tf(qlo.x), f2tf(qhi.x), f2tf(qlo.y), f2tf(qhi.y));
    }

    const long long gr0 = (long long)qt * 128 + w * 16 + gid;
    const long long gr1 = gr0 + 8;
    const float px0 = __ldg(pb + gr0 * 3), py0 = __ldg(pb + gr0 * 3 + 1), pz0 = __ldg(pb + gr0 * 3 + 2);
    const float px1 = __ldg(pb + gr1 * 3), py1 = __ldg(pb + gr1 * 3 + 1), pz1 = __ldg(pb + gr1 * 3 + 2);
    const float sq0 = px0 * px0 + py0 * py0 + pz0 * pz0;
    const float sq1 = px1 * px1 + py1 * py1 + pz1 * pz1;

    float oacc[16][4];
#pragma unroll
    for (int i = 0; i < 16; i++)
#pragma unroll
        for (int e = 0; e < 4; e++) oacc[i][e] = 0.f;
    float m0 = -1e30f, m1 = -1e30f, l0 = 0.f, l1 = 0.f;

    const float scale = 0.08838834764831845f;  // 1/sqrt(128)
    const float alpha = __ldg(alpha_p);
    const int src0 = (lane & ~3) | (tig >> 1);
    const int src1 = src0 + 2;
    const bool odd = (tig & 1);

    for (int j = 0; j < 16; j++) {
        __syncthreads();
        const float* Kp = Kb + (long long)j * 128 * D;
#pragma unroll
        for (int i = 0; i < 16; i++) {
            const int r = w + 8 * i;
            const float2 klo = *(const float2*)(Kp + (long long)r * D + fc0);
            const float2 khi = *(const float2*)(Kp + (long long)r * D + fc0 + 4);
            *(uint4*)&Ks[r][fsp] = make_uint4(f2tf(klo.x), f2tf(khi.x), f2tf(klo.y), f2tf(khi.y));
            const float2 vlo = *(const float2*)(Vb + (long long)r * S + j * 128 + fc0);
            const float2 vhi = *(const float2*)(Vb + (long long)r * S + j * 128 + fc0 + 4);
            *(uint4*)&Vs[r][fsp] = make_uint4(f2tf(vlo.x), f2tf(vhi.x), f2tf(vlo.y), f2tf(vhi.y));
        }
        if (tid < 128) {
            const long long c = (long long)j * 128 + tid;
            const float x = pb[c * 3], y = pb[c * 3 + 1], zz = pb[c * 3 + 2];
            spos[tid] = make_float4(x, y, zz, x * x + y * y + zz * zz);
        }
        __syncthreads();

        // ---- S = Q @ K^T ----
        float sacc[16][4];
#pragma unroll
        for (int i = 0; i < 16; i++)
#pragma unroll
            for (int e = 0; e < 4; e++) sacc[i][e] = 0.f;

        const int ra = w * 16 + gid;
#pragma unroll
        for (int g = 0; g < 16; g++) {
            const int co = g * 8 + tig * 2;
            const uint2 a0 = *(const uint2*)&Qs[ra][co];
            const uint2 a1 = *(const uint2*)&Qs[ra + 8][co];
            uint32_t af[4] = { a0.x, a1.x, a0.y, a1.y };
#pragma unroll
            for (int nt = 0; nt < 16; nt++) {
                const uint2 bb = *(const uint2*)&Ks[nt * 8 + gid][co];
                uint32_t bf[2] = { bb.x, bb.y };
                mma_tf32(sacc[nt], af, bf);
            }
        }

        // ---- bias + online softmax ----
        float nm0 = m0, nm1 = m1;
#pragma unroll
        for (int nt = 0; nt < 16; nt++) {
            const int c0 = nt * 8 + tig * 2;
            const float4 q0 = spos[c0];
            const float4 q1 = spos[c0 + 1];
            float d;
            d = fmaxf(sq0 + q0.w - 2.f * (px0 * q0.x + py0 * q0.y + pz0 * q0.z), 0.f);
            sacc[nt][0] = sacc[nt][0] * scale - alpha * d;
            d = fmaxf(sq0 + q1.w - 2.f * (px0 * q1.x + py0 * q1.y + pz0 * q1.z), 0.f);
            sacc[nt][1] = sacc[nt][1] * scale - alpha * d;
            d = fmaxf(sq1 + q0.w - 2.f * (px1 * q0.x + py1 * q0.y + pz1 * q0.z), 0.f);
            sacc[nt][2] = sacc[nt][2] * scale - alpha * d;
            d = fmaxf(sq1 + q1.w - 2.f * (px1 * q1.x + py1 * q1.y + pz1 * q1.z), 0.f);
            sacc[nt][3] = sacc[nt][3] * scale - alpha * d;
            nm0 = fmaxf(nm0, fmaxf(sacc[nt][0], sacc[nt][1]));
            nm1 = fmaxf(nm1, fmaxf(sacc[nt][2], sacc[nt][3]));
        }
        nm0 = fmaxf(nm0, __shfl_xor_sync(0xffffffffu, nm0, 1));
        nm0 = fmaxf(nm0, __shfl_xor_sync(0xffffffffu, nm0, 2));
        nm1 = fmaxf(nm1, __shfl_xor_sync(0xffffffffu, nm1, 1));
        nm1 = fmaxf(nm1, __shfl_xor_sync(0xffffffffu, nm1, 2));

        const float f0 = __expf(m0 - nm0);
        const float f1 = __expf(m1 - nm1);
        m0 = nm0; m1 = nm1;

        float rs0 = 0.f, rs1 = 0.f;
#pragma unroll
        for (int nt = 0; nt < 16; nt++) {
            sacc[nt][0] = __expf(sacc[nt][0] - nm0);
            sacc[nt][1] = __expf(sacc[nt][1] - nm0);
            sacc[nt][2] = __expf(sacc[nt][2] - nm1);
            sacc[nt][3] = __expf(sacc[nt][3] - nm1);
            rs0 += sacc[nt][0] + sacc[nt][1];
            rs1 += sacc[nt][2] + sacc[nt][3];
        }
        rs0 += __shfl_xor_sync(0xffffffffu, rs0, 1);
        rs0 += __shfl_xor_sync(0xffffffffu, rs0, 2);
        rs1 += __shfl_xor_sync(0xffffffffu, rs1, 1);
        rs1 += __shfl_xor_sync(0xffffffffu, rs1, 2);
        l0 = l0 * f0 + rs0;
        l1 = l1 * f1 + rs1;

#pragma unroll
        for (int i = 0; i < 16; i++) {
            oacc[i][0] *= f0; oacc[i][1] *= f0;
            oacc[i][2] *= f1; oacc[i][3] *= f1;
        }

        // ---- O += P @ V ----
#pragma unroll
        for (int g = 0; g < 16; g++) {
            const float u00 = __shfl_sync(0xffffffffu, sacc[g][0], src0);
            const float u01 = __shfl_sync(0xffffffffu, sacc[g][1], src0);
            const float u10 = __shfl_sync(0xffffffffu, sacc[g][0], src1);
            const float u11 = __shfl_sync(0xffffffffu, sacc[g][1], src1);
            const float u20 = __shfl_sync(0xffffffffu, sacc[g][2], src0);
            const float u21 = __shfl_sync(0xffffffffu, sacc[g][3], src0);
            const float u30 = __shfl_sync(0xffffffffu, sacc[g][2], src1);
            const float u31 = __shfl_sync(0xffffffffu, sacc[g][3], src1);
            uint32_t af[4];
            af[0] = f2tf(odd ? u01 : u00);   // P[row0][tig]
            af[1] = f2tf(odd ? u21 : u20);   // P[row1][tig]
            af[2] = f2tf(odd ? u11 : u10);   // P[row0][tig+4]
            af[3] = f2tf(odd ? u31 : u30);   // P[row1][tig+4]
            const int co = g * 8 + tig * 2;
#pragma unroll
            for (int ng = 0; ng < 16; ng++) {
                const uint2 bb = *(const uint2*)&Vs[ng * 8 + gid][co];
                uint32_t bf[2] = { bb.x, bb.y };
                mma_tf32(oacc[ng], af, bf);
            }
        }
    }

    // ---- epilogue: O / l -> ctx ----
    const float i0 = 1.f / l0, i1 = 1.f / l1;
    float* Cb = g_ctx + b * ((long long)S * D) + h * HD;
    const long long cr0 = (long long)qt * 128 + w * 16 + gid;
#pragma unroll
    for (int ng = 0; ng < 16; ng++) {
        const int col = ng * 8 + tig * 2;
        *(float2*)(Cb + cr0 * D + col)       = make_float2(oacc[ng][0] * i0, oacc[ng][1] * i0);
        *(float2*)(Cb + (cr0 + 8) * D + col) = make_float2(oacc[ng][2] * i1, oacc[ng][3] * i1);
    }
}

// ------------------------------------------------------------------ transpose [R,C] -> [C,R]
__global__ void transpose_kernel(const float* __restrict__ in, float* __restrict__ out,
                                 int R, int C)
{
    __shared__ float t[32][33];
    const int bx = blockIdx.x * 32, by = blockIdx.y * 32;
    const int tx = threadIdx.x, ty = threadIdx.y;
#pragma unroll
    for (int dy = 0; dy < 32; dy += 8)
        t[ty + dy][tx] = in[(size_t)(by + ty + dy) * C + bx + tx];
    __syncthreads();
#pragma unroll
    for (int dy = 0; dy < 32; dy += 8)
        out[(size_t)(bx + ty + dy) * R + by + tx] = t[tx][ty + dy];
}

// ------------------------------------------------------------------ LayerNorm
__global__ void ln_kernel(const float* __restrict__ x, const float* __restrict__ x2,
                          const float* __restrict__ gamma, const float* __restrict__ beta,
                          float* __restrict__ out)
{
    __shared__ float red[128];
    const int row = blockIdx.x, t = threadIdx.x;
    const size_t base = (size_t)row * D + t * 4;

    float4 v = *(const float4*)(x + base);
    if (x2) {
        float4 w = *(const float4*)(x2 + base);
        v.x += w.x; v.y += w.y; v.z += w.z; v.w += w.w;
    }
    red[t] = v.x + v.y + v.z + v.w; __syncthreads();
    for (int s2 = 64; s2 > 0; s2 >>= 1) {
        if (t < s2) red[t] += red[t + s2];
        __syncthreads();
    }
    const float mean = red[0] * (1.f / D); __syncthreads();

    float dx = v.x - mean, dy = v.y - mean, dz = v.z - mean, dw = v.w - mean;
    red[t] = dx * dx + dy * dy + dz * dz + dw * dw; __syncthreads();
    for (int s2 = 64; s2 > 0; s2 >>= 1) {
        if (t < s2) red[t] += red[t + s2];
        __syncthreads();
    }
    const float inv = rsqrtf(red[0] * (1.f / D) + LN_EPS);

    float4 g = *(const float4*)(gamma + t * 4);
    float4 bt = *(const float4*)(beta + t * 4);
    float4 o;
    o.x = dx * inv * g.x + bt.x;
    o.y = dy * inv * g.y + bt.y;
    o.z = dz * inv * g.z + bt.z;
    o.w = dw * inv * g.w + bt.w;
    *(float4*)(out + base) = o;
}

// ------------------------------------------------------------------ host
extern "C" void kernel_launch(void* const* d_in, const int* in_sizes, int n_in,
                              void* d_out, int out_size)
{
    const float* input   = (const float*)d_in[0];
    const float* pos     = (const float*)d_in[1];
    const float* We      = (const float*)d_in[2];
    const float* be      = (const float*)d_in[3];
    const float* Ws      = (const float*)d_in[4];
    const float* bs      = (const float*)d_in[5];
    const float* gamma   = (const float*)d_in[6];
    const float* beta    = (const float*)d_in[7];
    const float* Wq      = (const float*)d_in[8];
    const float* bq      = (const float*)d_in[9];
    const float* Wk      = (const float*)d_in[10];
    const float* bk      = (const float*)d_in[11];
    const float* Wv      = (const float*)d_in[12];
    const float* bv      = (const float*)d_in[13];
    const float* alpha_p = (const float*)d_in[14];
    float* out = (float*)d_out;

    float *h, *se_pre, *se, *qk, *vt, *ctx, *wet, *wst, *wqkv;
    cudaGetSymbolAddress((void**)&h,      g_h);
    cudaGetSymbolAddress((void**)&se_pre, g_se_pre);
    cudaGetSymbolAddress((void**)&se,     g_se);
    cudaGetSymbolAddress((void**)&qk,     g_qk);
    cudaGetSymbolAddress((void**)&vt,     g_vt);
    cudaGetSymbolAddress((void**)&ctx,    g_ctx);
    cudaGetSymbolAddress((void**)&wet,    g_wet);
    cudaGetSymbolAddress((void**)&wst,    g_wst);
    cudaGetSymbolAddress((void**)&wqkv,   g_wqkv);

    const int gemm_smem  = 4 * 128 * LDA * 4;                // 81920 B (double-buffered A+B)
    const int flash_smem = (3 * 128 * FLDA) * 4 + 128 * 16;  // 210944 B
    static bool attr_set = false;
    if (!attr_set) {
        cudaFuncSetAttribute(flash_kernel, cudaFuncAttributeMaxDynamicSharedMemorySize, flash_smem);
        cudaFuncSetAttribute(mma_gemm,     cudaFuncAttributeMaxDynamicSharedMemorySize, gemm_smem);
        attr_set = true;
    }

    dim3 tb(32, 8);
    transpose_kernel<<<dim3(D2 / 32, D / 32),  tb>>>(We, wet, D, D2);
    transpose_kernel<<<dim3(D / 32,  D2 / 32), tb>>>(Ws, wst, D2, D);
    transpose_kernel<<<dim3(D / 32,  D / 32),  tb>>>(Wq, wqkv + 0 * D * D, D, D);
    transpose_kernel<<<dim3(D / 32,  D / 32),  tb>>>(Wk, wqkv + 1 * D * D, D, D);
    transpose_kernel<<<dim3(D / 32,  D / 32),  tb>>>(Wv, wqkv + 2 * D * D, D, D);

    // 1. h = relu(input @ We + be)
    mma_gemm<<<dim3(D2 / 128, M_TOT / 128, 1), 256, gemm_smem>>>(
        input, D, 0, 0,  wet, D, 0, 0,  h, D2, 0, 0,
        be, be, be, nullptr, nullptr, -1, 1, D, 1);
    // 2. se_pre = input + h @ Ws + bs
    mma_gemm<<<dim3(D / 128, M_TOT / 128, 1), 256, gemm_smem>>>(
        h, D2, 0, 0,  wst, D2, 0, 0,  se_pre, D, 0, 0,
        bs, bs, bs, input, nullptr, -1, 0, D2, 1);
    // 3. se = LN(se_pre)
    ln_kernel<<<M_TOT, 128>>>(se_pre, nullptr, gamma, beta, se);
    // 4. q/k/v (z=0,1,2); v written transposed into g_vt
    mma_gemm<<<dim3(D / 128, M_TOT / 128, 3), 256, gemm_smem>>>(
        se, D, 0, 0,
        wqkv, D, (long long)D * D, 0,
        qk, D, (long long)M_TOT * D, 0,
        bq, bk, bv, nullptr, vt, 2, 0, D, 1);
    // 5-7. fused flash attention -> ctx
    flash_kernel<<<dim3(S / 128, Bb * H), 256, flash_smem>>>(
        qk, qk + (size_t)M_TOT * D, pos, alpha_p);
    // 8. out = LN(se + ctx)
    ln_kernel<<<M_TOT, 128>>>(se, ctx, gamma, beta, out);
}